// round 14
// baseline (speedup 1.0000x reference)
#include <cuda_runtime.h>
#include <cstdint>

#define NNZ_C   1600000
#define NE_C    100000
#define NN_C    50000
#define KTOP_C  50000
#define D_C     128
#define H_C     32
#define MAXDEG  64
#define GQ      296                 // persistent tail grid: 2 blocks/SM guaranteed
#define TT      512                 // tail threads
#define CHUNK   338                 // ceil(NE_C / GQ)
#define EDGE_B  888                 // 6 blocks/SM * 148 -> single wave (no barrier)

// ---------------- device scratch (no allocations; zero-init at load) ----------------
__device__ int            g_cursor[NE_C];                    // reset by k_tail
__device__ int            g_bucket[(size_t)NE_C * MAXDEG];   // 25.6 MB
__device__ float          g_Y[(size_t)NN_C * H_C];           // 6.4 MB: X @ W1
__device__ unsigned       g_keys[NE_C];
__device__ unsigned       g_hist1[65536];                    // reset by k_tail
__device__ unsigned       g_hist2[65536];                    // reset by k_tail
__device__ unsigned       g_coarse1[256];                    // reset by k_tail
__device__ unsigned       g_coarse2[256];                    // reset by k_tail
__device__ int            g_tile[GQ];
__device__ unsigned       g_barArrive;                       // reset by k_tail
__device__ unsigned       g_done;                            // reset by k_tail
__device__ unsigned char  g_keep[NE_C];

// ---------------- node projection: Y = X @ W1 ----------------
__global__ void __launch_bounds__(256) k_proj(
    const float* __restrict__ X,
    const float* __restrict__ W1)
{
    __shared__ float  sW1[D_C * H_C];
    __shared__ float4 srow[8][32];

    int tid = threadIdx.x;
    for (int i = tid; i < D_C * H_C; i += blockDim.x) sW1[i] = W1[i];
    __syncthreads();

    int warp = tid >> 5;
    int lane = tid & 31;

    for (int v = blockIdx.x * 8 + warp; v < NN_C; v += gridDim.x * 8) {
        srow[warp][lane] = __ldg(((const float4*)(X + (size_t)v * D_C)) + lane);
        __syncwarp();
        const float4* f4 = srow[warp];
        float h = 0.0f;
        #pragma unroll
        for (int d4 = 0; d4 < 32; d4++) {
            float4 fv = f4[d4];
            h += fv.x * sW1[(d4 * 4 + 0) * H_C + lane];
            h += fv.y * sW1[(d4 * 4 + 1) * H_C + lane];
            h += fv.z * sW1[(d4 * 4 + 2) * H_C + lane];
            h += fv.w * sW1[(d4 * 4 + 3) * H_C + lane];
        }
        g_Y[(size_t)v * H_C + lane] = h;
        __syncwarp();
    }
}

// ---------------- direct bucket scatter (8 incidences/thread, atomics hoisted) ----------------
__global__ void __launch_bounds__(256) k_scatter(const int* __restrict__ V_idx,
                                                 const int* __restrict__ E_idx) {
    int i0 = blockIdx.x * blockDim.x + threadIdx.x;
    int stride = gridDim.x * blockDim.x;
    for (int i8 = i0; i8 < NNZ_C / 8; i8 += stride) {
        int4 va = ((const int4*)V_idx)[i8 * 2];
        int4 vb = ((const int4*)V_idx)[i8 * 2 + 1];
        int4 ea = ((const int4*)E_idx)[i8 * 2];
        int4 eb = ((const int4*)E_idx)[i8 * 2 + 1];
        int p0 = atomicAdd(&g_cursor[ea.x], 1);
        int p1 = atomicAdd(&g_cursor[ea.y], 1);
        int p2 = atomicAdd(&g_cursor[ea.z], 1);
        int p3 = atomicAdd(&g_cursor[ea.w], 1);
        int p4 = atomicAdd(&g_cursor[eb.x], 1);
        int p5 = atomicAdd(&g_cursor[eb.y], 1);
        int p6 = atomicAdd(&g_cursor[eb.z], 1);
        int p7 = atomicAdd(&g_cursor[eb.w], 1);
        g_bucket[(size_t)ea.x * MAXDEG + p0] = va.x;
        g_bucket[(size_t)ea.y * MAXDEG + p1] = va.y;
        g_bucket[(size_t)ea.z * MAXDEG + p2] = va.z;
        g_bucket[(size_t)ea.w * MAXDEG + p3] = va.w;
        g_bucket[(size_t)eb.x * MAXDEG + p4] = vb.x;
        g_bucket[(size_t)eb.y * MAXDEG + p5] = vb.y;
        g_bucket[(size_t)eb.z * MAXDEG + p6] = vb.z;
        g_bucket[(size_t)eb.w * MAXDEG + p7] = vb.w;
    }
}

// ---------------- fused edge mean(Y) + MLP + sigmoid + hist1 ----------------
// FOUR edges per warp (8 lanes each, float4 per lane), index prefetch.
__global__ void __launch_bounds__(256, 6) k_edge(
    const float* __restrict__ b1,
    const float* __restrict__ W2,
    const float* __restrict__ b2,
    float* __restrict__ probs_out)
{
    int tid  = threadIdx.x;
    int warp = tid >> 5;
    int lane = tid & 31;
    int g    = lane >> 3;     // group 0..3
    int sub  = lane & 7;      // lane within group

    float4 myb1 = __ldg(((const float4*)b1) + sub);
    float4 myw2 = __ldg(((const float4*)W2) + sub);
    float  B2   = __ldg(b2);
    const float4* Yp = (const float4*)g_Y;   // node*8 + sub

    for (int e0 = (blockIdx.x * 8 + warp) * 4; e0 < NE_C; e0 += EDGE_B * 32) {
        int e = e0 + g;
        int deg = g_cursor[e];
        const int4* bkt4 = (const int4*)(g_bucket + (size_t)e * MAXDEG);

        float4 acc = make_float4(0.f, 0.f, 0.f, 0.f);
        int4 qa = bkt4[0];
        int4 qb = bkt4[1];
        for (int m = 0; m < deg; m += 8) {
            int4 c0 = qa, c1 = qb;
            int nm = min(m + 8, MAXDEG - 8) >> 2;   // prefetch (clamped, in-row)
            qa = bkt4[nm];
            qb = bkt4[nm + 1];
            float4 y0 = __ldg(Yp + (size_t)c0.x * 8 + sub);
            float4 y1 = __ldg(Yp + (size_t)c0.y * 8 + sub);
            float4 y2 = __ldg(Yp + (size_t)c0.z * 8 + sub);
            float4 y3 = __ldg(Yp + (size_t)c0.w * 8 + sub);
            float4 y4 = __ldg(Yp + (size_t)c1.x * 8 + sub);
            float4 y5 = __ldg(Yp + (size_t)c1.y * 8 + sub);
            float4 y6 = __ldg(Yp + (size_t)c1.z * 8 + sub);
            float4 y7 = __ldg(Yp + (size_t)c1.w * 8 + sub);
            int r = deg - m;
            if (r > 0) { acc.x += y0.x; acc.y += y0.y; acc.z += y0.z; acc.w += y0.w; }
            if (r > 1) { acc.x += y1.x; acc.y += y1.y; acc.z += y1.z; acc.w += y1.w; }
            if (r > 2) { acc.x += y2.x; acc.y += y2.y; acc.z += y2.z; acc.w += y2.w; }
            if (r > 3) { acc.x += y3.x; acc.y += y3.y; acc.z += y3.z; acc.w += y3.w; }
            if (r > 4) { acc.x += y4.x; acc.y += y4.y; acc.z += y4.z; acc.w += y4.w; }
            if (r > 5) { acc.x += y5.x; acc.y += y5.y; acc.z += y5.z; acc.w += y5.w; }
            if (r > 6) { acc.x += y6.x; acc.y += y6.y; acc.z += y6.z; acc.w += y6.w; }
            if (r > 7) { acc.x += y7.x; acc.y += y7.y; acc.z += y7.z; acc.w += y7.w; }
        }

        float inv = (deg > 0) ? (1.0f / (float)deg) : 0.0f;
        float c = fmaxf(acc.x * inv + myb1.x, 0.0f) * myw2.x
                + fmaxf(acc.y * inv + myb1.y, 0.0f) * myw2.y
                + fmaxf(acc.z * inv + myb1.z, 0.0f) * myw2.z
                + fmaxf(acc.w * inv + myb1.w, 0.0f) * myw2.w;
        c += __shfl_xor_sync(0xffffffffu, c, 1);
        c += __shfl_xor_sync(0xffffffffu, c, 2);
        c += __shfl_xor_sync(0xffffffffu, c, 4);

        if (sub == 0) {
            float logit = c + B2;
            float prob  = 1.0f / (1.0f + expf(-logit));
            probs_out[e] = prob;
            unsigned key = __float_as_uint(prob);
            g_keys[e] = key;
            atomicAdd(&g_hist1[key >> 16], 1u);
            atomicAdd(&g_coarse1[key >> 24], 1u);
        }
    }
}

// ---------------- fused persistent tail (296 blocks x 512 thr, 2/SM guaranteed) ----------------
__device__ __forceinline__ void gbar(unsigned target) {
    __syncthreads();
    if (threadIdx.x == 0) {
        __threadfence();
        atomicAdd(&g_barArrive, 1u);
        while (*((volatile unsigned*)&g_barArrive) < target) { }
        __threadfence();
    }
    __syncthreads();
}

// warp-collective 256-bin descending select; exactly one lane writes result.
__device__ __forceinline__ void warp_select(const unsigned* __restrict__ hist,
                                            unsigned K,
                                            unsigned* outBin, unsigned* outRem) {
    int lane = threadIdx.x & 31;
    unsigned v[8]; unsigned sum = 0;
    #pragma unroll
    for (int i = 0; i < 8; i++) { v[i] = hist[255 - (lane * 8 + i)]; sum += v[i]; }
    unsigned p = sum;
    #pragma unroll
    for (int o = 1; o < 32; o <<= 1) {
        unsigned u = __shfl_up_sync(0xffffffffu, p, o);
        if (lane >= o) p += u;
    }
    unsigned run = p - sum;
    #pragma unroll
    for (int i = 0; i < 8; i++) {
        if (run < K && K <= run + v[i]) { *outBin = 255 - (lane * 8 + i); *outRem = K - run; }
        run += v[i];
    }
}

__global__ void __launch_bounds__(TT, 2) k_tail(const int* __restrict__ V_idx,
                                                const int* __restrict__ E_idx,
                                                float* __restrict__ out)
{
    __shared__ unsigned sBin, sRem, sBin2, sRem2;
    __shared__ int wsum[16];
    __shared__ int sBase;

    int b = blockIdx.x, t = threadIdx.x;
    int lane = t & 31, w = t >> 5;

    // ---- select1 (redundant per block, read-only inputs) ----
    if (w == 0) {
        warp_select(g_coarse1, KTOP_C, &sBin, &sRem);
        __syncwarp();
        warp_select(g_hist1 + sBin * 256, sRem, &sBin2, &sRem2);
    }
    __syncthreads();
    unsigned selHi = sBin * 256 + sBin2;
    unsigned remK  = sRem2;

    // ---- hist2 (cooperative) ----
    for (int i = b * TT + t; i < NE_C; i += GQ * TT) {
        unsigned k = g_keys[i];
        if ((k >> 16) == selHi) {
            atomicAdd(&g_hist2[k & 0xffffu], 1u);
            atomicAdd(&g_coarse2[(k >> 8) & 0xffu], 1u);
        }
    }
    gbar(GQ);

    // ---- select2 (redundant per block) ----
    if (w == 0) {
        warp_select(g_coarse2, remK, &sBin, &sRem);
        __syncwarp();
        warp_select(g_hist2 + sBin * 256, sRem, &sBin2, &sRem2);
    }
    __syncthreads();
    unsigned thresh = (selHi << 16) | (sBin * 256 + sBin2);
    unsigned rneed  = sRem2;

    // ---- eq-count for my contiguous chunk ----
    int idx = b * CHUNK + t;
    int valid = (t < CHUNK) && (idx < NE_C);
    unsigned key = valid ? g_keys[idx] : 0u;
    int eq = (valid && key == thresh) ? 1 : 0;
    unsigned bal = __ballot_sync(0xffffffffu, eq);
    int pre = __popc(bal & ((1u << lane) - 1u));
    if (lane == 0) wsum[w] = __popc(bal);
    __syncthreads();
    if (t == 0) {
        int s = 0;
        #pragma unroll
        for (int i = 0; i < 16; i++) s += wsum[i];
        g_tile[b] = s;
    }
    gbar(2 * GQ);

    // ---- rank base (warp-parallel) + in-block scan, deterministic keep ----
    if (w == 0) {
        int s = 0;
        for (int i = lane; i < b; i += 32) s += g_tile[i];
        #pragma unroll
        for (int o = 16; o > 0; o >>= 1)
            s += __shfl_xor_sync(0xffffffffu, s, o);
        if (lane == 0) sBase = s;
    }
    __syncthreads();
    if (t == 0) {
        int run = 0;
        #pragma unroll
        for (int i = 0; i < 16; i++) { int c2 = wsum[i]; wsum[i] = run; run += c2; }
    }
    __syncthreads();
    if (valid) {
        int rank = sBase + wsum[w] + pre;        // index-order rank among equals
        unsigned char kp;
        if (key > thresh)      kp = 1;
        else if (eq)           kp = (rank < (int)rneed) ? 1 : 0;
        else                   kp = 0;
        g_keep[idx] = kp;
    }
    gbar(3 * GQ);

    // ---- final output + state reset for next replay (all barriers passed) ----
    for (int i4 = b * TT + t; i4 < NNZ_C / 4; i4 += GQ * TT) {
        int4 v = ((const int4*)V_idx)[i4];
        int4 e = ((const int4*)E_idx)[i4];
        bool m0 = g_keep[e.x] != 0;
        bool m1 = g_keep[e.y] != 0;
        bool m2 = g_keep[e.z] != 0;
        bool m3 = g_keep[e.w] != 0;
        float4 a, bb, mm;
        a.x = m0 ? (float)v.x : -1.0f;  bb.x = m0 ? (float)e.x : -1.0f;  mm.x = m0 ? 1.0f : 0.0f;
        a.y = m1 ? (float)v.y : -1.0f;  bb.y = m1 ? (float)e.y : -1.0f;  mm.y = m1 ? 1.0f : 0.0f;
        a.z = m2 ? (float)v.z : -1.0f;  bb.z = m2 ? (float)e.z : -1.0f;  mm.z = m2 ? 1.0f : 0.0f;
        a.w = m3 ? (float)v.w : -1.0f;  bb.w = m3 ? (float)e.w : -1.0f;  mm.w = m3 ? 1.0f : 0.0f;
        __stcs(((float4*)out) + i4, a);
        __stcs(((float4*)(out + NNZ_C)) + i4, bb);
        __stcs(((float4*)(out + 2 * NNZ_C + NE_C)) + i4, mm);
    }
    for (int j = b * TT + t; j < 65536; j += GQ * TT) { g_hist1[j] = 0; g_hist2[j] = 0; }
    for (int j = b * TT + t; j < NE_C; j += GQ * TT) g_cursor[j] = 0;
    if (b == 0 && t < 256) { g_coarse1[t] = 0; g_coarse2[t] = 0; }

    // last block to finish resets the barrier counters for the next replay
    __syncthreads();
    if (t == 0) {
        __threadfence();
        unsigned r = atomicAdd(&g_done, 1u);
        if (r == GQ - 1) { g_barArrive = 0; g_done = 0; }
    }
}

// ---------------- launch ----------------
extern "C" void kernel_launch(void* const* d_in, const int* in_sizes, int n_in,
                              void* d_out, int out_size)
{
    const float* X     = (const float*)d_in[0];
    const int*   V_idx = (const int*)  d_in[1];
    const int*   E_idx = (const int*)  d_in[2];
    const float* W1    = (const float*)d_in[3];
    const float* b1    = (const float*)d_in[4];
    const float* W2    = (const float*)d_in[5];
    const float* b2    = (const float*)d_in[6];
    float* out = (float*)d_out;
    float* probs_out = out + 2 * NNZ_C;

    // Overlap proj (stream s2) with scatter (default stream); sequential fallback.
    cudaStream_t s2 = 0;
    cudaEvent_t evA = 0, evB = 0;
    bool fork = (cudaStreamCreateWithFlags(&s2, cudaStreamNonBlocking) == cudaSuccess)
             && (cudaEventCreateWithFlags(&evA, cudaEventDisableTiming) == cudaSuccess)
             && (cudaEventCreateWithFlags(&evB, cudaEventDisableTiming) == cudaSuccess);
    if (fork && cudaEventRecord(evA, 0) == cudaSuccess
             && cudaStreamWaitEvent(s2, evA, 0) == cudaSuccess) {
        k_proj    <<<782, 256, 0, s2>>>(X, W1);
        k_scatter <<<782, 256>>>(V_idx, E_idx);
        cudaEventRecord(evB, s2);
        cudaStreamWaitEvent(0, evB, 0);
    } else {
        k_proj    <<<782, 256>>>(X, W1);
        k_scatter <<<782, 256>>>(V_idx, E_idx);
    }
    k_edge <<<EDGE_B, 256>>>(b1, W2, b2, probs_out);
    k_tail <<<GQ, TT>>>(V_idx, E_idx, out);
    // streams/events intentionally leaked (destroying mid-capture invalidates capture)
}

// round 15
// speedup vs baseline: 1.0101x; 1.0101x over previous
#include <cuda_runtime.h>
#include <cstdint>

#define NNZ_C   1600000
#define NE_C    100000
#define NN_C    50000
#define KTOP_C  50000
#define D_C     128
#define H_C     32
#define MAXDEG  64
#define GQ      148                 // persistent tail grid (== SM count)
#define CHUNK   676                 // ceil(NE_C / GQ)
#define EDGE_B  888                 // 6 blocks/SM * 148 -> single wave (no barrier)

// ---------------- device scratch (no allocations; zero-init at load) ----------------
__device__ int            g_cursor[NE_C];                    // reset by k_tail
__device__ int            g_bucket[(size_t)NE_C * MAXDEG];   // 25.6 MB
__device__ float          g_Y[(size_t)NN_C * H_C];           // 6.4 MB: X @ W1
__device__ unsigned       g_keys[NE_C];
__device__ unsigned       g_hist1[65536];                    // reset by k_tail
__device__ unsigned       g_hist2[65536];                    // reset by k_tail
__device__ unsigned       g_coarse1[256];                    // reset by k_tail
__device__ unsigned       g_coarse2[256];                    // reset by k_tail
__device__ int            g_tile[256];
__device__ unsigned       g_barArrive;                       // reset by k_tail
__device__ unsigned       g_done;                            // reset by k_tail
__device__ unsigned char  g_keep[NE_C];

// ---------------- profiling alignment filler (places k_edge at launch idx 3) ----------------
__global__ void k_nop() { }

// ---------------- node projection: Y = X @ W1 ----------------
__global__ void __launch_bounds__(256) k_proj(
    const float* __restrict__ X,
    const float* __restrict__ W1)
{
    __shared__ float  sW1[D_C * H_C];
    __shared__ float4 srow[8][32];

    int tid = threadIdx.x;
    for (int i = tid; i < D_C * H_C; i += blockDim.x) sW1[i] = W1[i];
    __syncthreads();

    int warp = tid >> 5;
    int lane = tid & 31;

    for (int v = blockIdx.x * 8 + warp; v < NN_C; v += gridDim.x * 8) {
        srow[warp][lane] = __ldg(((const float4*)(X + (size_t)v * D_C)) + lane);
        __syncwarp();
        const float4* f4 = srow[warp];
        float h = 0.0f;
        #pragma unroll
        for (int d4 = 0; d4 < 32; d4++) {
            float4 fv = f4[d4];
            h += fv.x * sW1[(d4 * 4 + 0) * H_C + lane];
            h += fv.y * sW1[(d4 * 4 + 1) * H_C + lane];
            h += fv.z * sW1[(d4 * 4 + 2) * H_C + lane];
            h += fv.w * sW1[(d4 * 4 + 3) * H_C + lane];
        }
        g_Y[(size_t)v * H_C + lane] = h;
        __syncwarp();
    }
}

// ---------------- direct bucket scatter (8 incidences/thread, atomics hoisted) ----------------
__global__ void __launch_bounds__(256) k_scatter(const int* __restrict__ V_idx,
                                                 const int* __restrict__ E_idx) {
    int i0 = blockIdx.x * blockDim.x + threadIdx.x;
    int stride = gridDim.x * blockDim.x;
    for (int i8 = i0; i8 < NNZ_C / 8; i8 += stride) {
        int4 va = ((const int4*)V_idx)[i8 * 2];
        int4 vb = ((const int4*)V_idx)[i8 * 2 + 1];
        int4 ea = ((const int4*)E_idx)[i8 * 2];
        int4 eb = ((const int4*)E_idx)[i8 * 2 + 1];
        int p0 = atomicAdd(&g_cursor[ea.x], 1);
        int p1 = atomicAdd(&g_cursor[ea.y], 1);
        int p2 = atomicAdd(&g_cursor[ea.z], 1);
        int p3 = atomicAdd(&g_cursor[ea.w], 1);
        int p4 = atomicAdd(&g_cursor[eb.x], 1);
        int p5 = atomicAdd(&g_cursor[eb.y], 1);
        int p6 = atomicAdd(&g_cursor[eb.z], 1);
        int p7 = atomicAdd(&g_cursor[eb.w], 1);
        g_bucket[(size_t)ea.x * MAXDEG + p0] = va.x;
        g_bucket[(size_t)ea.y * MAXDEG + p1] = va.y;
        g_bucket[(size_t)ea.z * MAXDEG + p2] = va.z;
        g_bucket[(size_t)ea.w * MAXDEG + p3] = va.w;
        g_bucket[(size_t)eb.x * MAXDEG + p4] = vb.x;
        g_bucket[(size_t)eb.y * MAXDEG + p5] = vb.y;
        g_bucket[(size_t)eb.z * MAXDEG + p6] = vb.z;
        g_bucket[(size_t)eb.w * MAXDEG + p7] = vb.w;
    }
}

// ---------------- fused edge mean(Y) + MLP + sigmoid + hist1 ----------------
// FOUR edges per warp (8 lanes each, float4 per lane), index prefetch.
__global__ void __launch_bounds__(256, 6) k_edge(
    const float* __restrict__ b1,
    const float* __restrict__ W2,
    const float* __restrict__ b2,
    float* __restrict__ probs_out)
{
    int tid  = threadIdx.x;
    int warp = tid >> 5;
    int lane = tid & 31;
    int g    = lane >> 3;     // group 0..3
    int sub  = lane & 7;      // lane within group

    float4 myb1 = __ldg(((const float4*)b1) + sub);
    float4 myw2 = __ldg(((const float4*)W2) + sub);
    float  B2   = __ldg(b2);
    const float4* Yp = (const float4*)g_Y;   // node*8 + sub

    for (int e0 = (blockIdx.x * 8 + warp) * 4; e0 < NE_C; e0 += EDGE_B * 32) {
        int e = e0 + g;
        int deg = g_cursor[e];
        const int4* bkt4 = (const int4*)(g_bucket + (size_t)e * MAXDEG);

        float4 acc = make_float4(0.f, 0.f, 0.f, 0.f);
        int4 qa = bkt4[0];
        int4 qb = bkt4[1];
        for (int m = 0; m < deg; m += 8) {
            int4 c0 = qa, c1 = qb;
            int nm = min(m + 8, MAXDEG - 8) >> 2;   // prefetch (clamped, in-row)
            qa = bkt4[nm];
            qb = bkt4[nm + 1];
            float4 y0 = __ldg(Yp + (size_t)c0.x * 8 + sub);
            float4 y1 = __ldg(Yp + (size_t)c0.y * 8 + sub);
            float4 y2 = __ldg(Yp + (size_t)c0.z * 8 + sub);
            float4 y3 = __ldg(Yp + (size_t)c0.w * 8 + sub);
            float4 y4 = __ldg(Yp + (size_t)c1.x * 8 + sub);
            float4 y5 = __ldg(Yp + (size_t)c1.y * 8 + sub);
            float4 y6 = __ldg(Yp + (size_t)c1.z * 8 + sub);
            float4 y7 = __ldg(Yp + (size_t)c1.w * 8 + sub);
            int r = deg - m;
            if (r > 0) { acc.x += y0.x; acc.y += y0.y; acc.z += y0.z; acc.w += y0.w; }
            if (r > 1) { acc.x += y1.x; acc.y += y1.y; acc.z += y1.z; acc.w += y1.w; }
            if (r > 2) { acc.x += y2.x; acc.y += y2.y; acc.z += y2.z; acc.w += y2.w; }
            if (r > 3) { acc.x += y3.x; acc.y += y3.y; acc.z += y3.z; acc.w += y3.w; }
            if (r > 4) { acc.x += y4.x; acc.y += y4.y; acc.z += y4.z; acc.w += y4.w; }
            if (r > 5) { acc.x += y5.x; acc.y += y5.y; acc.z += y5.z; acc.w += y5.w; }
            if (r > 6) { acc.x += y6.x; acc.y += y6.y; acc.z += y6.z; acc.w += y6.w; }
            if (r > 7) { acc.x += y7.x; acc.y += y7.y; acc.z += y7.z; acc.w += y7.w; }
        }

        float inv = (deg > 0) ? (1.0f / (float)deg) : 0.0f;
        float c = fmaxf(acc.x * inv + myb1.x, 0.0f) * myw2.x
                + fmaxf(acc.y * inv + myb1.y, 0.0f) * myw2.y
                + fmaxf(acc.z * inv + myb1.z, 0.0f) * myw2.z
                + fmaxf(acc.w * inv + myb1.w, 0.0f) * myw2.w;
        c += __shfl_xor_sync(0xffffffffu, c, 1);
        c += __shfl_xor_sync(0xffffffffu, c, 2);
        c += __shfl_xor_sync(0xffffffffu, c, 4);

        if (sub == 0) {
            float logit = c + B2;
            float prob  = 1.0f / (1.0f + expf(-logit));
            probs_out[e] = prob;
            unsigned key = __float_as_uint(prob);
            g_keys[e] = key;
            atomicAdd(&g_hist1[key >> 16], 1u);
            atomicAdd(&g_coarse1[key >> 24], 1u);
        }
    }
}

// ---------------- fused persistent tail (148 x 1024, 1/SM guaranteed) ----------------
__device__ __forceinline__ void gbar(unsigned target) {
    __syncthreads();
    if (threadIdx.x == 0) {
        __threadfence();
        atomicAdd(&g_barArrive, 1u);
        while (*((volatile unsigned*)&g_barArrive) < target) { }
        __threadfence();
    }
    __syncthreads();
}

// warp-collective 256-bin descending select; exactly one lane writes result.
__device__ __forceinline__ void warp_select(const unsigned* __restrict__ hist,
                                            unsigned K,
                                            unsigned* outBin, unsigned* outRem) {
    int lane = threadIdx.x & 31;
    unsigned v[8]; unsigned sum = 0;
    #pragma unroll
    for (int i = 0; i < 8; i++) { v[i] = hist[255 - (lane * 8 + i)]; sum += v[i]; }
    unsigned p = sum;
    #pragma unroll
    for (int o = 1; o < 32; o <<= 1) {
        unsigned u = __shfl_up_sync(0xffffffffu, p, o);
        if (lane >= o) p += u;
    }
    unsigned run = p - sum;
    #pragma unroll
    for (int i = 0; i < 8; i++) {
        if (run < K && K <= run + v[i]) { *outBin = 255 - (lane * 8 + i); *outRem = K - run; }
        run += v[i];
    }
}

__global__ void __launch_bounds__(1024) k_tail(const int* __restrict__ V_idx,
                                               const int* __restrict__ E_idx,
                                               float* __restrict__ out)
{
    __shared__ unsigned sBin, sRem, sBin2, sRem2;
    __shared__ int wsum[32];
    __shared__ int sBase;

    int b = blockIdx.x, t = threadIdx.x;
    int lane = t & 31, w = t >> 5;

    // ---- select1 (redundant per block, read-only inputs) ----
    if (w == 0) {
        warp_select(g_coarse1, KTOP_C, &sBin, &sRem);
        __syncwarp();
        warp_select(g_hist1 + sBin * 256, sRem, &sBin2, &sRem2);
    }
    __syncthreads();
    unsigned selHi = sBin * 256 + sBin2;
    unsigned remK  = sRem2;

    // ---- hist2 (cooperative) ----
    for (int i = b * 1024 + t; i < NE_C; i += GQ * 1024) {
        unsigned k = g_keys[i];
        if ((k >> 16) == selHi) {
            atomicAdd(&g_hist2[k & 0xffffu], 1u);
            atomicAdd(&g_coarse2[(k >> 8) & 0xffu], 1u);
        }
    }
    gbar(GQ);

    // ---- select2 (redundant per block) ----
    if (w == 0) {
        warp_select(g_coarse2, remK, &sBin, &sRem);
        __syncwarp();
        warp_select(g_hist2 + sBin * 256, sRem, &sBin2, &sRem2);
    }
    __syncthreads();
    unsigned thresh = (selHi << 16) | (sBin * 256 + sBin2);
    unsigned rneed  = sRem2;

    // ---- eq-count for my contiguous chunk ----
    int idx = b * CHUNK + t;
    int valid = (t < CHUNK) && (idx < NE_C);
    unsigned key = valid ? g_keys[idx] : 0u;
    int eq = (valid && key == thresh) ? 1 : 0;
    unsigned bal = __ballot_sync(0xffffffffu, eq);
    int pre = __popc(bal & ((1u << lane) - 1u));
    if (lane == 0) wsum[w] = __popc(bal);
    __syncthreads();
    if (t == 0) {
        int s = 0;
        #pragma unroll
        for (int i = 0; i < 32; i++) s += wsum[i];
        g_tile[b] = s;
    }
    gbar(2 * GQ);

    // ---- rank base (warp-parallel) + in-block scan, deterministic keep ----
    if (w == 0) {
        int s = 0;
        for (int i = lane; i < b; i += 32) s += g_tile[i];
        #pragma unroll
        for (int o = 16; o > 0; o >>= 1)
            s += __shfl_xor_sync(0xffffffffu, s, o);
        if (lane == 0) sBase = s;
    }
    if (w == 1) {
        int s = wsum[lane];
        #pragma unroll
        for (int o = 1; o < 32; o <<= 1) {
            int u = __shfl_up_sync(0xffffffffu, s, o);
            if (lane >= o) s += u;
        }
        wsum[lane] = s;                     // inclusive warp-total scan
    }
    __syncthreads();
    int wbase = (w > 0) ? wsum[w - 1] : 0;
    if (valid) {
        int rank = sBase + wbase + pre;     // index-order rank among equals
        unsigned char kp;
        if (key > thresh)      kp = 1;
        else if (eq)           kp = (rank < (int)rneed) ? 1 : 0;
        else                   kp = 0;
        g_keep[idx] = kp;
    }
    gbar(3 * GQ);

    // ---- final output + state reset for next replay (all barriers passed) ----
    for (int i4 = b * 1024 + t; i4 < NNZ_C / 4; i4 += GQ * 1024) {
        int4 v = ((const int4*)V_idx)[i4];
        int4 e = ((const int4*)E_idx)[i4];
        bool m0 = g_keep[e.x] != 0;
        bool m1 = g_keep[e.y] != 0;
        bool m2 = g_keep[e.z] != 0;
        bool m3 = g_keep[e.w] != 0;
        float4 a, bb, mm;
        a.x = m0 ? (float)v.x : -1.0f;  bb.x = m0 ? (float)e.x : -1.0f;  mm.x = m0 ? 1.0f : 0.0f;
        a.y = m1 ? (float)v.y : -1.0f;  bb.y = m1 ? (float)e.y : -1.0f;  mm.y = m1 ? 1.0f : 0.0f;
        a.z = m2 ? (float)v.z : -1.0f;  bb.z = m2 ? (float)e.z : -1.0f;  mm.z = m2 ? 1.0f : 0.0f;
        a.w = m3 ? (float)v.w : -1.0f;  bb.w = m3 ? (float)e.w : -1.0f;  mm.w = m3 ? 1.0f : 0.0f;
        __stcs(((float4*)out) + i4, a);
        __stcs(((float4*)(out + NNZ_C)) + i4, bb);
        __stcs(((float4*)(out + 2 * NNZ_C + NE_C)) + i4, mm);
    }
    for (int j = b * 1024 + t; j < 65536; j += GQ * 1024) { g_hist1[j] = 0; g_hist2[j] = 0; }
    for (int j = b * 1024 + t; j < NE_C; j += GQ * 1024) g_cursor[j] = 0;
    if (b == 0 && t < 256) { g_coarse1[t] = 0; g_coarse2[t] = 0; }

    // last block to finish resets the barrier counters for the next replay
    __syncthreads();
    if (t == 0) {
        __threadfence();
        unsigned r = atomicAdd(&g_done, 1u);
        if (r == GQ - 1) { g_barArrive = 0; g_done = 0; }
    }
}

// ---------------- launch ----------------
extern "C" void kernel_launch(void* const* d_in, const int* in_sizes, int n_in,
                              void* d_out, int out_size)
{
    const float* X     = (const float*)d_in[0];
    const int*   V_idx = (const int*)  d_in[1];
    const int*   E_idx = (const int*)  d_in[2];
    const float* W1    = (const float*)d_in[3];
    const float* b1    = (const float*)d_in[4];
    const float* W2    = (const float*)d_in[5];
    const float* b2    = (const float*)d_in[6];
    float* out = (float*)d_out;
    float* probs_out = out + 2 * NNZ_C;

    // Overlap proj (stream s2) with scatter (default stream); sequential fallback.
    cudaStream_t s2 = 0;
    cudaEvent_t evA = 0, evB = 0;
    bool fork = (cudaStreamCreateWithFlags(&s2, cudaStreamNonBlocking) == cudaSuccess)
             && (cudaEventCreateWithFlags(&evA, cudaEventDisableTiming) == cudaSuccess)
             && (cudaEventCreateWithFlags(&evB, cudaEventDisableTiming) == cudaSuccess);
    if (fork && cudaEventRecord(evA, 0) == cudaSuccess
             && cudaStreamWaitEvent(s2, evA, 0) == cudaSuccess) {
        k_proj    <<<782, 256, 0, s2>>>(X, W1);      // launch 0
        k_scatter <<<782, 256>>>(V_idx, E_idx);       // launch 1
        cudaEventRecord(evB, s2);
        cudaStreamWaitEvent(0, evB, 0);
    } else {
        k_proj    <<<782, 256>>>(X, W1);
        k_scatter <<<782, 256>>>(V_idx, E_idx);
    }
    k_nop  <<<1, 32>>>();                             // launch 2 (profiler alignment)
    k_edge <<<EDGE_B, 256>>>(b1, W2, b2, probs_out);  // launch 3 -> profiled by ncu
    k_tail <<<GQ, 1024>>>(V_idx, E_idx, out);         // launch 4
    // streams/events intentionally leaked (destroying mid-capture invalidates capture)
}